// round 5
// baseline (speedup 1.0000x reference)
#include <cuda_runtime.h>

// 2-layer LSTM + linear head + clip. B=256 T=2048 I=32 H=64.
// Kernel 1 (xg_kernel): xg[t][b][row] = x@Wih0^T + b_ih0 + b_hh0 (parallel).
// Kernel 2 (lstm2_kernel): 128 CTAs x 512 thr; CTA = 2 batch elements over all
//   2048 steps. Thread pair (even,odd lane) splits gate row r = (p%4)*64+p/4,
//   p = tid/2: even lane: L1 cols 0..31 + Wih1 row; odd: L1 cols 32..63 + Whh1
//   row. Partial preacts combined via shfl.xor(1). 8-lane unit-group: lanes 0-3
//   run batch0 cell, 4-7 batch1. ONE barrier/step (h1,h2 double-buffered).
//   h2 streamed to global; kernel 3 (yhead) does y = h2@Wout + clip.
// Smem bank plan: act halves offset 36 floats (=144B = 16 mod 128 -> the two
//   broadcast addresses of each LDS.128 hit disjoint banks); h2 base +296
//   floats (=32B mod 128); weight stride 14 ull (28i mod 32 distinct).

#define TT 2048
#define NB 256
#define NI 32

typedef unsigned long long ull;

__device__ float g_xg[TT * NB * 256];   // [t][b][row-permuted]
__device__ float g_h2[(size_t)NB * TT * 64];    // [b][t][h]

__device__ __forceinline__ float sigmf(float v) {
    return __fdividef(1.f, 1.f + __expf(-v));
}
__device__ __forceinline__ void fma2(ull& d, ull a, ull b) {
    asm("fma.rn.f32x2 %0, %1, %2, %0;" : "+l"(d) : "l"(a), "l"(b));
}
__device__ __forceinline__ ull add2(ull a, ull b) {
    ull r; asm("add.rn.f32x2 %0, %1, %2;" : "=l"(r) : "l"(a), "l"(b)); return r;
}
__device__ __forceinline__ float2 unpk(ull v) {
    float2 r; asm("mov.b64 {%0, %1}, %2;" : "=f"(r.x), "=f"(r.y) : "l"(v)); return r;
}
__device__ __forceinline__ ull pk(float a, float b) {
    ull r; asm("mov.b64 %0, {%1, %2};" : "=l"(r) : "f"(a), "f"(b)); return r;
}
// gates pre-activated: gi,gf,go = sigmoid, gg = tanh
__device__ __forceinline__ float cell_rest(float gi, float gf, float gg, float go, float& c) {
    c = fmaf(gf, c, gi * gg);
    return go * fmaf(2.f, sigmf(2.f * c), -1.f);   // o * tanh(c)
}

// ---------------- Kernel 1: xg precompute ----------------
__global__ void __launch_bounds__(256, 1)
xg_kernel(const float* __restrict__ x,
          const float* __restrict__ Wih0,
          const float* __restrict__ bih0, const float* __restrict__ bhh0)
{
    __shared__ float xt[4][64 * NI];   // 32 KB
    const int tid = threadIdx.x;
    const int t0 = (blockIdx.x & 31) * 64;
    const int b0 = (blockIdx.x >> 5) * 4;
    const int r  = ((tid & 3) << 6) | (tid >> 2);

    #pragma unroll
    for (int b = 0; b < 4; b++) {
        const float4* src = (const float4*)(x + ((size_t)(b0 + b) * TT + t0) * NI);
        float4* dst = (float4*)xt[b];
        for (int i = tid; i < 64 * NI / 4; i += 256) dst[i] = src[i];
    }

    ull w[16];
    {
        const ulonglong2* W = (const ulonglong2*)(Wih0 + r * NI);
        #pragma unroll
        for (int k = 0; k < 8; k++) { ulonglong2 v = W[k]; w[2*k] = v.x; w[2*k+1] = v.y; }
    }
    const float bias = bih0[r] + bhh0[r];
    __syncthreads();

    #pragma unroll
    for (int b = 0; b < 4; b++) {
        float* dst = g_xg + ((size_t)t0 * NB + (b0 + b)) * 256 + tid;
        #pragma unroll 4
        for (int t = 0; t < 64; t++) {
            const ulonglong2* v = (const ulonglong2*)(xt[b] + t * NI);
            ull aA = pk(bias, 0.f), aB = 0ull;
            #pragma unroll
            for (int c = 0; c < 8; c++) {
                ulonglong2 u = v[c];
                fma2(aA, w[2*c],   u.x);
                fma2(aB, w[2*c+1], u.y);
            }
            float2 s = unpk(add2(aA, aB));
            dst[(size_t)t * NB * 256] = s.x + s.y;
        }
    }
}

// ---------------- Kernel 2: recurrent loop ----------------
__global__ void __launch_bounds__(512, 1)
lstm2_kernel(const float* __restrict__ Whh0,
             const float* __restrict__ Wih1, const float* __restrict__ Whh1,
             const float* __restrict__ bih1, const float* __restrict__ bhh1)
{
    extern __shared__ ull smu[];
    // [0 .. 512*14) ull : per-thread layer-2 smem weight packs (12 used of 14)
    float* actf = (float*)(smu + 512 * 14);
    float* h1s  = actf;          // [2 buf][2 batch][72] : halves at +0 / +36
    float* h2s  = actf + 296;    // same structure, +296 floats (32B mod 128)

    const int tid  = threadIdx.x;
    const int lane = tid & 31;
    const int half = tid & 1;                 // 0: low cols / Wih1, 1: high / Whh1
    const int p    = tid >> 1;                // row owner 0..255
    const int q    = p & 3;                   // gate 0=i 1=f 2=g 3=o
    const int r    = (q << 6) | (p >> 2);     // weight-matrix row
    const int h    = tid >> 3;                // hidden unit 0..63
    const int bb   = blockIdx.x << 1;
    const int wpos = h + ((h >= 32) ? 4 : 0); // padded column slot
    const int sb8  = (lane & ~7) | ((lane >> 2) & 1);   // gather source base
    const unsigned FULL = 0xffffffffu;

    const ull b2p = pk(bih1[r] + bhh1[r], 0.f);
    const float kml = (q == 2) ? 2.f : 1.f;   // act = msc*sigm(kml*A)+mad
    const float msc = (q == 2) ? 2.f : 1.f;
    const float mad = (q == 2) ? -1.f : 0.f;

    // ---- weights ----
    ull w1p[16];   // Whh0 row r, cols [half*32, half*32+32)
    {
        const ulonglong2* W = (const ulonglong2*)(Whh0 + r * 64 + half * 32);
        #pragma unroll
        for (int k = 0; k < 8; k++) { ulonglong2 v = W[k]; w1p[2*k] = v.x; w1p[2*k+1] = v.y; }
    }
    ull w2p[20];   // layer-2 row (Wih1 if half==0 else Whh1): packs 0..19
    {
        const ulonglong2* W = (const ulonglong2*)((half ? Whh1 : Wih1) + r * 64);
        #pragma unroll
        for (int k = 0; k < 10; k++) { ulonglong2 v = W[k]; w2p[2*k] = v.x; w2p[2*k+1] = v.y; }
        ulonglong2* RWw = (ulonglong2*)(smu + tid * 14);    // packs 20..31
        #pragma unroll
        for (int k = 0; k < 6; k++) RWw[k] = W[10 + k];
    }

    for (int i = tid; i < 600; i += 512) actf[i] = 0.f;
    __syncthreads();

    float c1 = 0.f, c2 = 0.f;     // cell state for MY batch (lane&4 ? b1 : b0)
    const ulonglong2* RW = (const ulonglong2*)(smu + tid * 14);

    float xc0 = 0.f, xc1 = 0.f;
    if (!half) {
        const float* g0 = g_xg + (size_t)bb * 256 + p;
        xc0 = g0[0]; xc1 = g0[256];
    }

    for (int t = 0; t < TT; ++t) {
        float xn0 = 0.f, xn1 = 0.f;
        if (!half && t + 1 < TT) {
            const float* gp = g_xg + ((size_t)(t + 1) * NB + bb) * 256 + p;
            xn0 = gp[0]; xn1 = gp[256];
        }

        // ---- layer 1: my 32-col half of the recurrent dot, both batches ----
        const float* pb = h1s + ((t + 1) & 1) * 144 + half * 36;
        ull aA0 = half ? 0ull : pk(xc0, 0.f), aB0 = 0ull;
        ull aA1 = half ? 0ull : pk(xc1, 0.f), aB1 = 0ull;
        #pragma unroll
        for (int k = 0; k < 8; k++) {
            ulonglong2 ua = *(const ulonglong2*)(pb + k * 4);
            ulonglong2 ub = *(const ulonglong2*)(pb + 72 + k * 4);
            fma2(aA0, w1p[2*k],   ua.x);
            fma2(aB0, w1p[2*k+1], ua.y);
            fma2(aA1, w1p[2*k],   ub.x);
            fma2(aB1, w1p[2*k+1], ub.y);
        }
        float2 s0 = unpk(add2(aA0, aB0));
        float2 s1 = unpk(add2(aA1, aB1));
        float A0h = s0.x + s0.y, A1h = s1.x + s1.y;
        float A0 = A0h + __shfl_xor_sync(FULL, A0h, 1);
        float A1 = A1h + __shfl_xor_sync(FULL, A1h, 1);
        float act0 = fmaf(msc, sigmf(kml * A0), mad);
        float act1 = fmaf(msc, sigmf(kml * A1), mad);
        float v = (lane & 1) ? act1 : act0;
        float gi = __shfl_sync(FULL, v, sb8 + 0);
        float gf = __shfl_sync(FULL, v, sb8 + 2);
        float gg = __shfl_sync(FULL, v, sb8 + 4);
        float go = __shfl_sync(FULL, v, sb8 + 6);
        float h1v = cell_rest(gi, gf, gg, go, c1);
        if ((lane & 7) == 0) h1s[(t & 1) * 144 + wpos]      = h1v;   // batch0
        if ((lane & 7) == 4) h1s[(t & 1) * 144 + 72 + wpos] = h1v;   // batch1

        __syncthreads();   // the single per-step barrier

        // ---- layer 2: even lanes Wih1 . h1_t, odd lanes Whh1 . h2_{t-1} ----
        const float* sb = half ? (h2s + ((t + 1) & 1) * 144)
                               : (h1s + (t & 1) * 144);
        ull binit = half ? 0ull : b2p;
        ull bA0 = binit, bB0 = 0ull, bA1 = binit, bB1 = 0ull;
        #pragma unroll
        for (int k = 0; k < 10; k++) {
            int off = k * 4 + ((k >= 8) ? 4 : 0);
            ulonglong2 ua = *(const ulonglong2*)(sb + off);
            ulonglong2 ub = *(const ulonglong2*)(sb + 72 + off);
            fma2(bA0, w2p[2*k],   ua.x);
            fma2(bB0, w2p[2*k+1], ua.y);
            fma2(bA1, w2p[2*k],   ub.x);
            fma2(bB1, w2p[2*k+1], ub.y);
        }
        #pragma unroll
        for (int k = 0; k < 6; k++) {
            ulonglong2 wv = RW[k];
            int off = (k + 10) * 4 + 4;
            ulonglong2 ua = *(const ulonglong2*)(sb + off);
            ulonglong2 ub = *(const ulonglong2*)(sb + 72 + off);
            fma2(bA0, wv.x, ua.x);
            fma2(bB0, wv.y, ua.y);
            fma2(bA1, wv.x, ub.x);
            fma2(bB1, wv.y, ub.y);
        }
        float2 u0 = unpk(add2(bA0, bB0));
        float2 u1 = unpk(add2(bA1, bB1));
        float B0h = u0.x + u0.y, B1h = u1.x + u1.y;
        float B0 = B0h + __shfl_xor_sync(FULL, B0h, 1);
        float B1 = B1h + __shfl_xor_sync(FULL, B1h, 1);
        float bact0 = fmaf(msc, sigmf(kml * B0), mad);
        float bact1 = fmaf(msc, sigmf(kml * B1), mad);
        float w2v = (lane & 1) ? bact1 : bact0;
        float Gi = __shfl_sync(FULL, w2v, sb8 + 0);
        float Gf = __shfl_sync(FULL, w2v, sb8 + 2);
        float Gg = __shfl_sync(FULL, w2v, sb8 + 4);
        float Go = __shfl_sync(FULL, w2v, sb8 + 6);
        float h2v = cell_rest(Gi, Gf, Gg, Go, c2);
        if ((lane & 7) == 0) {
            h2s[(t & 1) * 144 + wpos] = h2v;
            g_h2[((size_t)bb * TT + t) * 64 + h] = h2v;
        }
        if ((lane & 7) == 4) {
            h2s[(t & 1) * 144 + 72 + wpos] = h2v;
            g_h2[(((size_t)bb + 1) * TT + t) * 64 + h] = h2v;
        }

        xc0 = xn0; xc1 = xn1;
    }
}

// ---------------- Kernel 3: y head ----------------
__global__ void __launch_bounds__(256, 1)
yhead_kernel(const float* __restrict__ Wout, const float* __restrict__ bOut,
             float* __restrict__ out)
{
    __shared__ float w[64];
    __shared__ float bsh;
    if (threadIdx.x < 64) w[threadIdx.x] = Wout[threadIdx.x];
    if (threadIdx.x == 0) bsh = bOut[0];
    __syncthreads();

    int idx = blockIdx.x * 256 + threadIdx.x;     // 0 .. 524287  ([b][t])
    const float* hp = g_h2 + (size_t)idx * 64;
    float s = bsh;
    #pragma unroll
    for (int k = 0; k < 16; k++) {
        float4 vv = *(const float4*)(hp + 4 * k);
        s += vv.x * w[4*k] + vv.y * w[4*k+1] + vv.z * w[4*k+2] + vv.w * w[4*k+3];
    }
    out[idx] = fminf(fmaxf(s, 0.f), 1.f);
}

extern "C" void kernel_launch(void* const* d_in, const int* in_sizes, int n_in,
                              void* d_out, int out_size)
{
    (void)in_sizes; (void)n_in; (void)out_size;
    const float* x    = (const float*)d_in[0];
    const float* Wih0 = (const float*)d_in[1];
    const float* Whh0 = (const float*)d_in[2];
    const float* bih0 = (const float*)d_in[3];
    const float* bhh0 = (const float*)d_in[4];
    const float* Wih1 = (const float*)d_in[5];
    const float* Whh1 = (const float*)d_in[6];
    const float* bih1 = (const float*)d_in[7];
    const float* bhh1 = (const float*)d_in[8];
    const float* Wout = (const float*)d_in[9];
    const float* bOut = (const float*)d_in[10];
    float* out = (float*)d_out;

    xg_kernel<<<2048, 256>>>(x, Wih0, bih0, bhh0);

    const int smem = 512 * 14 * (int)sizeof(ull) + 600 * (int)sizeof(float);
    cudaFuncSetAttribute(lstm2_kernel, cudaFuncAttributeMaxDynamicSharedMemorySize, smem);
    lstm2_kernel<<<128, 512, smem>>>(Whh0, Wih1, Whh1, bih1, bhh1);

    yhead_kernel<<<2048, 256>>>(Wout, bOut, out);
}

// round 6
// speedup vs baseline: 1.0610x; 1.0610x over previous
#include <cuda_runtime.h>

// 2-layer LSTM + linear head + clip. B=256 T=2048 I=32 H=64.
// Kernel 1 (xg_kernel): xg[t][b][row] = x@Wih0^T + b_ih0 + b_hh0 (parallel).
// Kernel 2 (lstm2_kernel): 128 CTAs x 512 thr; CTA = 2 batch elements over all
//   2048 steps. Thread pair (even,odd lane) splits gate row r = (p%4)*64+p/4,
//   p = tid/2: even lane: L1 cols 0..31 + Wih1 row; odd: L1 cols 32..63 + Whh1
//   row. Partials combined via shfl.xor(1). 8-lane unit-group: lanes 0-3 run
//   batch0 cell, 4-7 batch1. ONE barrier/step (h1,h2 double-buffered).
//   ALL 48 weight packs register-resident (no distinct-address LDS in loop;
//   remaining smem traffic is pure broadcasts). h2 streamed to global;
//   kernel 3 (yhead) does y = h2@Wout + clip.

#define TT 2048
#define NB 256
#define NI 32

typedef unsigned long long ull;

__device__ float g_xg[TT * NB * 256];           // [t][b][row-permuted]
__device__ float g_h2[(size_t)NB * TT * 64];    // [b][t][h]

__device__ __forceinline__ float sigmf(float v) {
    return __fdividef(1.f, 1.f + __expf(-v));
}
__device__ __forceinline__ void fma2(ull& d, ull a, ull b) {
    asm("fma.rn.f32x2 %0, %1, %2, %0;" : "+l"(d) : "l"(a), "l"(b));
}
__device__ __forceinline__ float2 unpk(ull v) {
    float2 r; asm("mov.b64 {%0, %1}, %2;" : "=f"(r.x), "=f"(r.y) : "l"(v)); return r;
}
__device__ __forceinline__ ull pk(float a, float b) {
    ull r; asm("mov.b64 %0, {%1, %2};" : "=l"(r) : "f"(a), "f"(b)); return r;
}
// gates pre-activated: gi,gf,go = sigmoid, gg = tanh
__device__ __forceinline__ float cell_rest(float gi, float gf, float gg, float go, float& c) {
    c = fmaf(gf, c, gi * gg);
    return go * fmaf(2.f, sigmf(2.f * c), -1.f);   // o * tanh(c)
}

// ---------------- Kernel 1: xg precompute ----------------
__global__ void __launch_bounds__(256, 1)
xg_kernel(const float* __restrict__ x,
          const float* __restrict__ Wih0,
          const float* __restrict__ bih0, const float* __restrict__ bhh0)
{
    __shared__ float xt[4][64 * NI];   // 32 KB
    const int tid = threadIdx.x;
    const int t0 = (blockIdx.x & 31) * 64;
    const int b0 = (blockIdx.x >> 5) * 4;
    const int r  = ((tid & 3) << 6) | (tid >> 2);

    #pragma unroll
    for (int b = 0; b < 4; b++) {
        const float4* src = (const float4*)(x + ((size_t)(b0 + b) * TT + t0) * NI);
        float4* dst = (float4*)xt[b];
        for (int i = tid; i < 64 * NI / 4; i += 256) dst[i] = src[i];
    }

    ull w[16];
    {
        const ulonglong2* W = (const ulonglong2*)(Wih0 + r * NI);
        #pragma unroll
        for (int k = 0; k < 8; k++) { ulonglong2 v = W[k]; w[2*k] = v.x; w[2*k+1] = v.y; }
    }
    const float bias = bih0[r] + bhh0[r];
    __syncthreads();

    #pragma unroll
    for (int b = 0; b < 4; b++) {
        float* dst = g_xg + ((size_t)t0 * NB + (b0 + b)) * 256 + tid;
        #pragma unroll 4
        for (int t = 0; t < 64; t++) {
            const ulonglong2* v = (const ulonglong2*)(xt[b] + t * NI);
            ull aA = pk(bias, 0.f), aB = 0ull;
            #pragma unroll
            for (int c = 0; c < 8; c++) {
                ulonglong2 u = v[c];
                fma2(aA, w[2*c],   u.x);
                fma2(aB, w[2*c+1], u.y);
            }
            float2 sa = unpk(aA), sb = unpk(aB);
            dst[(size_t)t * NB * 256] = (sa.x + sa.y) + (sb.x + sb.y);
        }
    }
}

// ---------------- Kernel 2: recurrent loop ----------------
__global__ void __launch_bounds__(512, 1)
lstm2_kernel(const float* __restrict__ Whh0,
             const float* __restrict__ Wih1, const float* __restrict__ Whh1,
             const float* __restrict__ bih1, const float* __restrict__ bhh1)
{
    __shared__ __align__(16) float actf[600];
    float* h1s = actf;          // [2 buf][2 batch][72] : halves at +0 / +36
    float* h2s = actf + 296;    // same structure

    const int tid  = threadIdx.x;
    const int lane = tid & 31;
    const int half = tid & 1;                 // 0: low cols / Wih1, 1: high / Whh1
    const int p    = tid >> 1;                // row owner 0..255
    const int q    = p & 3;                   // gate 0=i 1=f 2=g 3=o
    const int r    = (q << 6) | (p >> 2);     // weight-matrix row
    const int h    = tid >> 3;                // hidden unit 0..63
    const int bb   = blockIdx.x << 1;
    const int wpos = h + ((h >= 32) ? 4 : 0); // padded column slot
    const int sb8  = (lane & ~7) | ((lane >> 2) & 1);   // gather source base
    const unsigned FULL = 0xffffffffu;

    const ull b2p = pk(bih1[r] + bhh1[r], 0.f);
    const float kml = (q == 2) ? 2.f : 1.f;   // act = msc*sigm(kml*A)+mad
    const float msc = (q == 2) ? 2.f : 1.f;
    const float mad = (q == 2) ? -1.f : 0.f;

    // ---- weights: ALL in registers ----
    ull w1p[16];   // Whh0 row r, cols [half*32, half*32+32)
    {
        const ulonglong2* W = (const ulonglong2*)(Whh0 + r * 64 + half * 32);
        #pragma unroll
        for (int k = 0; k < 8; k++) { ulonglong2 v = W[k]; w1p[2*k] = v.x; w1p[2*k+1] = v.y; }
    }
    ull w2p[32];   // layer-2 row (Wih1 if half==0 else Whh1), all 64 cols
    {
        const ulonglong2* W = (const ulonglong2*)((half ? Whh1 : Wih1) + r * 64);
        #pragma unroll
        for (int k = 0; k < 16; k++) { ulonglong2 v = W[k]; w2p[2*k] = v.x; w2p[2*k+1] = v.y; }
    }

    for (int i = tid; i < 600; i += 512) actf[i] = 0.f;
    __syncthreads();

    float c1 = 0.f, c2 = 0.f;     // cell state for MY batch (lane&4 ? b1 : b0)

    float xc0 = 0.f, xc1 = 0.f;
    if (!half) {
        const float* g0 = g_xg + (size_t)bb * 256 + p;
        xc0 = g0[0]; xc1 = g0[256];
    }

    for (int t = 0; t < TT; ++t) {
        float xn0 = 0.f, xn1 = 0.f;
        if (!half && t + 1 < TT) {
            const float* gp = g_xg + ((size_t)(t + 1) * NB + bb) * 256 + p;
            xn0 = gp[0]; xn1 = gp[256];
        }

        // ---- layer 1: my 32-col half of the recurrent dot, both batches ----
        const float* pb = h1s + ((t + 1) & 1) * 144 + half * 36;
        ull aA0 = half ? 0ull : pk(xc0, 0.f);
        ull aA1 = half ? 0ull : pk(xc1, 0.f);
        #pragma unroll
        for (int k = 0; k < 8; k++) {
            ulonglong2 ua = *(const ulonglong2*)(pb + k * 4);
            ulonglong2 ub = *(const ulonglong2*)(pb + 72 + k * 4);
            fma2(aA0, w1p[2*k],   ua.x);
            fma2(aA0, w1p[2*k+1], ua.y);
            fma2(aA1, w1p[2*k],   ub.x);
            fma2(aA1, w1p[2*k+1], ub.y);
        }
        float2 s0 = unpk(aA0);
        float2 s1 = unpk(aA1);
        float A0h = s0.x + s0.y, A1h = s1.x + s1.y;
        float A0 = A0h + __shfl_xor_sync(FULL, A0h, 1);
        float A1 = A1h + __shfl_xor_sync(FULL, A1h, 1);
        float act0 = fmaf(msc, sigmf(kml * A0), mad);
        float act1 = fmaf(msc, sigmf(kml * A1), mad);
        float v = (lane & 1) ? act1 : act0;
        float gi = __shfl_sync(FULL, v, sb8 + 0);
        float gf = __shfl_sync(FULL, v, sb8 + 2);
        float gg = __shfl_sync(FULL, v, sb8 + 4);
        float go = __shfl_sync(FULL, v, sb8 + 6);
        float h1v = cell_rest(gi, gf, gg, go, c1);
        if ((lane & 7) == 0) h1s[(t & 1) * 144 + wpos]      = h1v;   // batch0
        if ((lane & 7) == 4) h1s[(t & 1) * 144 + 72 + wpos] = h1v;   // batch1

        __syncthreads();   // the single per-step barrier

        // ---- layer 2: even lanes Wih1 . h1_t, odd lanes Whh1 . h2_{t-1} ----
        const float* sb = half ? (h2s + ((t + 1) & 1) * 144)
                               : (h1s + (t & 1) * 144);
        ull bA0 = half ? 0ull : b2p;
        ull bA1 = half ? 0ull : b2p;
        #pragma unroll
        for (int k = 0; k < 16; k++) {
            int off = k * 4 + ((k >= 8) ? 4 : 0);
            ulonglong2 ua = *(const ulonglong2*)(sb + off);
            ulonglong2 ub = *(const ulonglong2*)(sb + 72 + off);
            fma2(bA0, w2p[2*k],   ua.x);
            fma2(bA0, w2p[2*k+1], ua.y);
            fma2(bA1, w2p[2*k],   ub.x);
            fma2(bA1, w2p[2*k+1], ub.y);
        }
        float2 u0 = unpk(bA0);
        float2 u1 = unpk(bA1);
        float B0h = u0.x + u0.y, B1h = u1.x + u1.y;
        float B0 = B0h + __shfl_xor_sync(FULL, B0h, 1);
        float B1 = B1h + __shfl_xor_sync(FULL, B1h, 1);
        float bact0 = fmaf(msc, sigmf(kml * B0), mad);
        float bact1 = fmaf(msc, sigmf(kml * B1), mad);
        float w2v = (lane & 1) ? bact1 : bact0;
        float Gi = __shfl_sync(FULL, w2v, sb8 + 0);
        float Gf = __shfl_sync(FULL, w2v, sb8 + 2);
        float Gg = __shfl_sync(FULL, w2v, sb8 + 4);
        float Go = __shfl_sync(FULL, w2v, sb8 + 6);
        float h2v = cell_rest(Gi, Gf, Gg, Go, c2);
        if ((lane & 7) == 0) {
            h2s[(t & 1) * 144 + wpos] = h2v;
            g_h2[((size_t)bb * TT + t) * 64 + h] = h2v;
        }
        if ((lane & 7) == 4) {
            h2s[(t & 1) * 144 + 72 + wpos] = h2v;
            g_h2[(((size_t)bb + 1) * TT + t) * 64 + h] = h2v;
        }

        xc0 = xn0; xc1 = xn1;
    }
}

// ---------------- Kernel 3: y head ----------------
__global__ void __launch_bounds__(256, 1)
yhead_kernel(const float* __restrict__ Wout, const float* __restrict__ bOut,
             float* __restrict__ out)
{
    __shared__ float w[64];
    __shared__ float bsh;
    if (threadIdx.x < 64) w[threadIdx.x] = Wout[threadIdx.x];
    if (threadIdx.x == 0) bsh = bOut[0];
    __syncthreads();

    int idx = blockIdx.x * 256 + threadIdx.x;     // 0 .. 524287  ([b][t])
    const float* hp = g_h2 + (size_t)idx * 64;
    float s = bsh;
    #pragma unroll
    for (int k = 0; k < 16; k++) {
        float4 vv = *(const float4*)(hp + 4 * k);
        s += vv.x * w[4*k] + vv.y * w[4*k+1] + vv.z * w[4*k+2] + vv.w * w[4*k+3];
    }
    out[idx] = fminf(fmaxf(s, 0.f), 1.f);
}

extern "C" void kernel_launch(void* const* d_in, const int* in_sizes, int n_in,
                              void* d_out, int out_size)
{
    (void)in_sizes; (void)n_in; (void)out_size;
    const float* x    = (const float*)d_in[0];
    const float* Wih0 = (const float*)d_in[1];
    const float* Whh0 = (const float*)d_in[2];
    const float* bih0 = (const float*)d_in[3];
    const float* bhh0 = (const float*)d_in[4];
    const float* Wih1 = (const float*)d_in[5];
    const float* Whh1 = (const float*)d_in[6];
    const float* bih1 = (const float*)d_in[7];
    const float* bhh1 = (const float*)d_in[8];
    const float* Wout = (const float*)d_in[9];
    const float* bOut = (const float*)d_in[10];
    float* out = (float*)d_out;

    xg_kernel<<<2048, 256>>>(x, Wih0, bih0, bhh0);
    lstm2_kernel<<<128, 512>>>(Whh0, Wih1, Whh1, bih1, bhh1);
    yhead_kernel<<<2048, 256>>>(Wout, bOut, out);
}

// round 7
// speedup vs baseline: 1.0625x; 1.0014x over previous
#include <cuda_runtime.h>

// 2-layer LSTM + linear head + clip. B=256 T=2048 I=32 H=64.
// Kernel 1 (xg_kernel): xg[t][b][row] = x@Wih0^T + b_ih0 + b_hh0 (parallel).
// Kernel 2 (lstm2_kernel): 128 CTAs x 512 thr; CTA = 2 batch elements over all
//   2048 steps. Thread pair (even,odd lane) splits gate row r = (p%4)*64+p/4,
//   p = tid/2: even lane: L1 cols 0..31 + Wih1 row; odd: L1 cols 32..63 + Whh1
//   row. Partials combined via shfl.xor(1). 8-lane unit-group: lanes 0-3 run
//   batch0 cell, 4-7 batch1. ONE barrier/step (h1,h2 double-buffered).
//   ALL 48 weight packs register-resident (no distinct-address LDS in loop;
//   remaining smem traffic is pure broadcasts). h2 streamed to global;
//   kernel 3 (yhead) does y = h2@Wout + clip.

#define TT 2048
#define NB 256
#define NI 32

typedef unsigned long long ull;

__device__ float g_xg[TT * NB * 256];           // [t][b][row-permuted]
__device__ float g_h2[(size_t)NB * TT * 64];    // [b][t][h]

__device__ __forceinline__ float sigmf(float v) {
    return __fdividef(1.f, 1.f + __expf(-v));
}
__device__ __forceinline__ void fma2(ull& d, ull a, ull b) {
    asm("fma.rn.f32x2 %0, %1, %2, %0;" : "+l"(d) : "l"(a), "l"(b));
}
__device__ __forceinline__ float2 unpk(ull v) {
    float2 r; asm("mov.b64 {%0, %1}, %2;" : "=f"(r.x), "=f"(r.y) : "l"(v)); return r;
}
__device__ __forceinline__ ull pk(float a, float b) {
    ull r; asm("mov.b64 %0, {%1, %2};" : "=l"(r) : "f"(a), "f"(b)); return r;
}
// gates pre-activated: gi,gf,go = sigmoid, gg = tanh
__device__ __forceinline__ float cell_rest(float gi, float gf, float gg, float go, float& c) {
    c = fmaf(gf, c, gi * gg);
    return go * fmaf(2.f, sigmf(2.f * c), -1.f);   // o * tanh(c)
}

// ---------------- Kernel 1: xg precompute ----------------
__global__ void __launch_bounds__(256, 1)
xg_kernel(const float* __restrict__ x,
          const float* __restrict__ Wih0,
          const float* __restrict__ bih0, const float* __restrict__ bhh0)
{
    __shared__ float xt[4][64 * NI];   // 32 KB
    const int tid = threadIdx.x;
    const int t0 = (blockIdx.x & 31) * 64;
    const int b0 = (blockIdx.x >> 5) * 4;
    const int r  = ((tid & 3) << 6) | (tid >> 2);

    #pragma unroll
    for (int b = 0; b < 4; b++) {
        const float4* src = (const float4*)(x + ((size_t)(b0 + b) * TT + t0) * NI);
        float4* dst = (float4*)xt[b];
        for (int i = tid; i < 64 * NI / 4; i += 256) dst[i] = src[i];
    }

    ull w[16];
    {
        const ulonglong2* W = (const ulonglong2*)(Wih0 + r * NI);
        #pragma unroll
        for (int k = 0; k < 8; k++) { ulonglong2 v = W[k]; w[2*k] = v.x; w[2*k+1] = v.y; }
    }
    const float bias = bih0[r] + bhh0[r];
    __syncthreads();

    #pragma unroll
    for (int b = 0; b < 4; b++) {
        float* dst = g_xg + ((size_t)t0 * NB + (b0 + b)) * 256 + tid;
        #pragma unroll 4
        for (int t = 0; t < 64; t++) {
            const ulonglong2* v = (const ulonglong2*)(xt[b] + t * NI);
            ull aA = pk(bias, 0.f), aB = 0ull;
            #pragma unroll
            for (int c = 0; c < 8; c++) {
                ulonglong2 u = v[c];
                fma2(aA, w[2*c],   u.x);
                fma2(aB, w[2*c+1], u.y);
            }
            float2 sa = unpk(aA), sb = unpk(aB);
            dst[(size_t)t * NB * 256] = (sa.x + sa.y) + (sb.x + sb.y);
        }
    }
}

// ---------------- Kernel 2: recurrent loop ----------------
__global__ void __launch_bounds__(512, 1)
lstm2_kernel(const float* __restrict__ Whh0,
             const float* __restrict__ Wih1, const float* __restrict__ Whh1,
             const float* __restrict__ bih1, const float* __restrict__ bhh1)
{
    __shared__ __align__(16) float actf[600];
    float* h1s = actf;          // [2 buf][2 batch][72] : halves at +0 / +36
    float* h2s = actf + 296;    // same structure

    const int tid  = threadIdx.x;
    const int lane = tid & 31;
    const int half = tid & 1;                 // 0: low cols / Wih1, 1: high / Whh1
    const int p    = tid >> 1;                // row owner 0..255
    const int q    = p & 3;                   // gate 0=i 1=f 2=g 3=o
    const int r    = (q << 6) | (p >> 2);     // weight-matrix row
    const int h    = tid >> 3;                // hidden unit 0..63
    const int bb   = blockIdx.x << 1;
    const int wpos = h + ((h >= 32) ? 4 : 0); // padded column slot
    const int sb8  = (lane & ~7) | ((lane >> 2) & 1);   // gather source base
    const unsigned FULL = 0xffffffffu;

    const ull b2p = pk(bih1[r] + bhh1[r], 0.f);
    const float kml = (q == 2) ? 2.f : 1.f;   // act = msc*sigm(kml*A)+mad
    const float msc = (q == 2) ? 2.f : 1.f;
    const float mad = (q == 2) ? -1.f : 0.f;

    // ---- weights: ALL in registers ----
    ull w1p[16];   // Whh0 row r, cols [half*32, half*32+32)
    {
        const ulonglong2* W = (const ulonglong2*)(Whh0 + r * 64 + half * 32);
        #pragma unroll
        for (int k = 0; k < 8; k++) { ulonglong2 v = W[k]; w1p[2*k] = v.x; w1p[2*k+1] = v.y; }
    }
    ull w2p[32];   // layer-2 row (Wih1 if half==0 else Whh1), all 64 cols
    {
        const ulonglong2* W = (const ulonglong2*)((half ? Whh1 : Wih1) + r * 64);
        #pragma unroll
        for (int k = 0; k < 16; k++) { ulonglong2 v = W[k]; w2p[2*k] = v.x; w2p[2*k+1] = v.y; }
    }

    for (int i = tid; i < 600; i += 512) actf[i] = 0.f;
    __syncthreads();

    float c1 = 0.f, c2 = 0.f;     // cell state for MY batch (lane&4 ? b1 : b0)

    float xc0 = 0.f, xc1 = 0.f;
    if (!half) {
        const float* g0 = g_xg + (size_t)bb * 256 + p;
        xc0 = g0[0]; xc1 = g0[256];
    }

    for (int t = 0; t < TT; ++t) {
        float xn0 = 0.f, xn1 = 0.f;
        if (!half && t + 1 < TT) {
            const float* gp = g_xg + ((size_t)(t + 1) * NB + bb) * 256 + p;
            xn0 = gp[0]; xn1 = gp[256];
        }

        // ---- layer 1: my 32-col half of the recurrent dot, both batches ----
        const float* pb = h1s + ((t + 1) & 1) * 144 + half * 36;
        ull aA0 = half ? 0ull : pk(xc0, 0.f);
        ull aA1 = half ? 0ull : pk(xc1, 0.f);
        #pragma unroll
        for (int k = 0; k < 8; k++) {
            ulonglong2 ua = *(const ulonglong2*)(pb + k * 4);
            ulonglong2 ub = *(const ulonglong2*)(pb + 72 + k * 4);
            fma2(aA0, w1p[2*k],   ua.x);
            fma2(aA0, w1p[2*k+1], ua.y);
            fma2(aA1, w1p[2*k],   ub.x);
            fma2(aA1, w1p[2*k+1], ub.y);
        }
        float2 s0 = unpk(aA0);
        float2 s1 = unpk(aA1);
        float A0h = s0.x + s0.y, A1h = s1.x + s1.y;
        float A0 = A0h + __shfl_xor_sync(FULL, A0h, 1);
        float A1 = A1h + __shfl_xor_sync(FULL, A1h, 1);
        float act0 = fmaf(msc, sigmf(kml * A0), mad);
        float act1 = fmaf(msc, sigmf(kml * A1), mad);
        float v = (lane & 1) ? act1 : act0;
        float gi = __shfl_sync(FULL, v, sb8 + 0);
        float gf = __shfl_sync(FULL, v, sb8 + 2);
        float gg = __shfl_sync(FULL, v, sb8 + 4);
        float go = __shfl_sync(FULL, v, sb8 + 6);
        float h1v = cell_rest(gi, gf, gg, go, c1);
        if ((lane & 7) == 0) h1s[(t & 1) * 144 + wpos]      = h1v;   // batch0
        if ((lane & 7) == 4) h1s[(t & 1) * 144 + 72 + wpos] = h1v;   // batch1

        __syncthreads();   // the single per-step barrier

        // ---- layer 2: even lanes Wih1 . h1_t, odd lanes Whh1 . h2_{t-1} ----
        const float* sb = half ? (h2s + ((t + 1) & 1) * 144)
                               : (h1s + (t & 1) * 144);
        ull bA0 = half ? 0ull : b2p;
        ull bA1 = half ? 0ull : b2p;
        #pragma unroll
        for (int k = 0; k < 16; k++) {
            int off = k * 4 + ((k >= 8) ? 4 : 0);
            ulonglong2 ua = *(const ulonglong2*)(sb + off);
            ulonglong2 ub = *(const ulonglong2*)(sb + 72 + off);
            fma2(bA0, w2p[2*k],   ua.x);
            fma2(bA0, w2p[2*k+1], ua.y);
            fma2(bA1, w2p[2*k],   ub.x);
            fma2(bA1, w2p[2*k+1], ub.y);
        }
        float2 u0 = unpk(bA0);
        float2 u1 = unpk(bA1);
        float B0h = u0.x + u0.y, B1h = u1.x + u1.y;
        float B0 = B0h + __shfl_xor_sync(FULL, B0h, 1);
        float B1 = B1h + __shfl_xor_sync(FULL, B1h, 1);
        float bact0 = fmaf(msc, sigmf(kml * B0), mad);
        float bact1 = fmaf(msc, sigmf(kml * B1), mad);
        float w2v = (lane & 1) ? bact1 : bact0;
        float Gi = __shfl_sync(FULL, w2v, sb8 + 0);
        float Gf = __shfl_sync(FULL, w2v, sb8 + 2);
        float Gg = __shfl_sync(FULL, w2v, sb8 + 4);
        float Go = __shfl_sync(FULL, w2v, sb8 + 6);
        float h2v = cell_rest(Gi, Gf, Gg, Go, c2);
        if ((lane & 7) == 0) {
            h2s[(t & 1) * 144 + wpos] = h2v;
            g_h2[((size_t)bb * TT + t) * 64 + h] = h2v;
        }
        if ((lane & 7) == 4) {
            h2s[(t & 1) * 144 + 72 + wpos] = h2v;
            g_h2[(((size_t)bb + 1) * TT + t) * 64 + h] = h2v;
        }

        xc0 = xn0; xc1 = xn1;
    }
}

// ---------------- Kernel 3: y head ----------------
__global__ void __launch_bounds__(256, 1)
yhead_kernel(const float* __restrict__ Wout, const float* __restrict__ bOut,
             float* __restrict__ out)
{
    __shared__ float w[64];
    __shared__ float bsh;
    if (threadIdx.x < 64) w[threadIdx.x] = Wout[threadIdx.x];
    if (threadIdx.x == 0) bsh = bOut[0];
    __syncthreads();

    int idx = blockIdx.x * 256 + threadIdx.x;     // 0 .. 524287  ([b][t])
    const float* hp = g_h2 + (size_t)idx * 64;
    float s = bsh;
    #pragma unroll
    for (int k = 0; k < 16; k++) {
        float4 vv = *(const float4*)(hp + 4 * k);
        s += vv.x * w[4*k] + vv.y * w[4*k+1] + vv.z * w[4*k+2] + vv.w * w[4*k+3];
    }
    out[idx] = fminf(fmaxf(s, 0.f), 1.f);
}

extern "C" void kernel_launch(void* const* d_in, const int* in_sizes, int n_in,
                              void* d_out, int out_size)
{
    (void)in_sizes; (void)n_in; (void)out_size;
    const float* x    = (const float*)d_in[0];
    const float* Wih0 = (const float*)d_in[1];
    const float* Whh0 = (const float*)d_in[2];
    const float* bih0 = (const float*)d_in[3];
    const float* bhh0 = (const float*)d_in[4];
    const float* Wih1 = (const float*)d_in[5];
    const float* Whh1 = (const float*)d_in[6];
    const float* bih1 = (const float*)d_in[7];
    const float* bhh1 = (const float*)d_in[8];
    const float* Wout = (const float*)d_in[9];
    const float* bOut = (const float*)d_in[10];
    float* out = (float*)d_out;

    xg_kernel<<<2048, 256>>>(x, Wih0, bih0, bhh0);
    lstm2_kernel<<<128, 512>>>(Whh0, Wih1, Whh1, bih1, bhh1);
    yhead_kernel<<<2048, 256>>>(Wout, bOut, out);
}

// round 9
// speedup vs baseline: 1.1271x; 1.0608x over previous
#include <cuda_runtime.h>

// 2-layer LSTM + linear head + clip. B=256 T=2048 I=32 H=64.
// K1: xg[t][b][row] = x@Wih0^T + biases (parallel).
// K2: 128 CTAs x 512 thr, CTA = 2 batches, persistent over 2048 steps.
//   L1 (R=1): thread pair (tid&1) splits gate row p=tid>>1 into 32-col halves;
//     xor(1) combine; 8-lane unit group: lanes 0-3 batch0 cell, 4-7 batch1.
//   L2 (R=2): thread owns rows rA=gp*128+u, rB=rA+64 (gate pair (i,f)|(g,o)),
//     chunk k=lane&3 (32 cols of concat [h1|h2]), both batches. 16 LDS.128.
//     xor(2) reduce + xor(1) reduce-scatter -> lane owns
//     (gate = 2*gp + (k>>1), batch = k&1); gather = sb2 + {0,2,4,6}.
//   tanh.approx.f32 activations. ONE barrier/step; h1,h2 double-buffered.
//   Bank plan: h2 base 288 (=0 mod 32 words); h1/h2 read bufs always opposite
//   parity (stride 144 = 16 mod 32) -> L2's 8 addrs hit disjoint banks.
// K3: y = h2@Wout + b, clip.

#define TT 2048
#define NB 256
#define NI 32

typedef unsigned long long ull;

__device__ float g_xg[TT * NB * 256];           // [t][b][row-permuted]
__device__ float g_h2[(size_t)NB * TT * 64];    // [b][t][h]

__device__ __forceinline__ float tanhapx(float v) {
    float r; asm("tanh.approx.f32 %0, %1;" : "=f"(r) : "f"(v)); return r;
}
__device__ __forceinline__ void fma2(ull& d, ull a, ull b) {
    asm("fma.rn.f32x2 %0, %1, %2, %0;" : "+l"(d) : "l"(a), "l"(b));
}
__device__ __forceinline__ float2 unpk(ull v) {
    float2 r; asm("mov.b64 {%0, %1}, %2;" : "=f"(r.x), "=f"(r.y) : "l"(v)); return r;
}
__device__ __forceinline__ ull pk(float a, float b) {
    ull r; asm("mov.b64 %0, {%1, %2};" : "=l"(r) : "f"(a), "f"(b)); return r;
}
// gates pre-activated: gi,gf,go = sigmoid, gg = tanh
__device__ __forceinline__ float cell_rest(float gi, float gf, float gg, float go, float& c) {
    c = fmaf(gf, c, gi * gg);
    return go * tanhapx(c);
}

// ---------------- Kernel 1: xg precompute ----------------
__global__ void __launch_bounds__(256, 1)
xg_kernel(const float* __restrict__ x,
          const float* __restrict__ Wih0,
          const float* __restrict__ bih0, const float* __restrict__ bhh0)
{
    __shared__ float xt[4][64 * NI];   // 32 KB
    const int tid = threadIdx.x;
    const int t0 = (blockIdx.x & 31) * 64;
    const int b0 = (blockIdx.x >> 5) * 4;
    const int r  = ((tid & 3) << 6) | (tid >> 2);

    #pragma unroll
    for (int b = 0; b < 4; b++) {
        const float4* src = (const float4*)(x + ((size_t)(b0 + b) * TT + t0) * NI);
        float4* dst = (float4*)xt[b];
        for (int i = tid; i < 64 * NI / 4; i += 256) dst[i] = src[i];
    }

    ull w[16];
    {
        const ulonglong2* W = (const ulonglong2*)(Wih0 + r * NI);
        #pragma unroll
        for (int k = 0; k < 8; k++) { ulonglong2 v = W[k]; w[2*k] = v.x; w[2*k+1] = v.y; }
    }
    const float bias = bih0[r] + bhh0[r];
    __syncthreads();

    #pragma unroll
    for (int b = 0; b < 4; b++) {
        float* dst = g_xg + ((size_t)t0 * NB + (b0 + b)) * 256 + tid;
        #pragma unroll 4
        for (int t = 0; t < 64; t++) {
            const ulonglong2* v = (const ulonglong2*)(xt[b] + t * NI);
            ull aA = pk(bias, 0.f), aB = 0ull;
            #pragma unroll
            for (int c = 0; c < 8; c++) {
                ulonglong2 u = v[c];
                fma2(aA, w[2*c],   u.x);
                fma2(aB, w[2*c+1], u.y);
            }
            float2 sa = unpk(aA), sb = unpk(aB);
            dst[(size_t)t * NB * 256] = (sa.x + sa.y) + (sb.x + sb.y);
        }
    }
}

// ---------------- Kernel 2: recurrent loop ----------------
__global__ void __launch_bounds__(512, 1)
lstm2_kernel(const float* __restrict__ Whh0,
             const float* __restrict__ Wih1, const float* __restrict__ Whh1,
             const float* __restrict__ bih1, const float* __restrict__ bhh1)
{
    // h1: [2 buf][2 batch][72] at 0..287 ; h2: same at 288..575
    __shared__ __align__(16) float actf[576];
    float* h1s = actf;
    float* h2s = actf + 288;

    const int tid  = threadIdx.x;
    const int lane = tid & 31;
    const unsigned FULL = 0xffffffffu;
    const int bb   = blockIdx.x << 1;

    // ---- layer-1 decomposition ----
    const int half = tid & 1;
    const int p    = tid >> 1;                  // L1 row owner 0..255
    const int q1   = p & 3;                     // gate
    const int r1   = (q1 << 6) | (p >> 2);      // weight row
    const int h    = tid >> 3;                  // hidden unit 0..63
    const int wpos = h + ((h >= 32) ? 4 : 0);
    const int sb1  = (lane & ~7) | ((lane >> 2) & 1);
    const float km1 = (q1 == 2) ? 1.f : 0.5f;   // act = ms*tanh(km*A)+md
    const float ms1 = (q1 == 2) ? 1.f : 0.5f;
    const float md1 = (q1 == 2) ? 0.f : 0.5f;

    // ---- layer-2 decomposition (R=2) ----
    const int k2  = lane & 3;                   // col chunk 0..3
    const int gp  = (lane >> 2) & 1;            // row pair (i,f)=0 / (g,o)=1
    const int rA  = gp * 128 + h;
    const int rB  = rA + 64;
    const int g2  = 2 * gp + (k2 >> 1);         // owned gate after reduce
    const int rown = (g2 << 6) + h;
    const int ob2 = k2 & 1;                     // owned batch
    const int sb2 = (lane & ~7) | ob2;
    const int j8  = lane & 7;
    const float km2 = (g2 == 2) ? 1.f : 0.5f;
    const float ms2 = (g2 == 2) ? 1.f : 0.5f;
    const float md2 = (g2 == 2) ? 0.f : 0.5f;
    const float bias2 = bih1[rown] + bhh1[rown];

    // ---- weights (all registers) ----
    ull w1p[16];   // Whh0 row r1, cols [32*half, +32)
    {
        const ulonglong2* W = (const ulonglong2*)(Whh0 + r1 * 64 + half * 32);
        #pragma unroll
        for (int k = 0; k < 8; k++) { ulonglong2 v = W[k]; w1p[2*k] = v.x; w1p[2*k+1] = v.y; }
    }
    ull wA[16], wB[16];  // L2 rows rA,rB, cols [32*(k2&1), +32) of Wih1 (k2<2) / Whh1
    {
        const float* Wsrc = (k2 < 2) ? Wih1 : Whh1;
        const int coff = (k2 & 1) * 32;
        const ulonglong2* WAp = (const ulonglong2*)(Wsrc + rA * 64 + coff);
        const ulonglong2* WBp = (const ulonglong2*)(Wsrc + rB * 64 + coff);
        #pragma unroll
        for (int k = 0; k < 8; k++) {
            ulonglong2 va = WAp[k]; wA[2*k] = va.x; wA[2*k+1] = va.y;
            ulonglong2 vb = WBp[k]; wB[2*k] = vb.x; wB[2*k+1] = vb.y;
        }
    }

    for (int i = tid; i < 576; i += 512) actf[i] = 0.f;
    __syncthreads();

    float c1 = 0.f, c2 = 0.f;   // c1: batch (lane>>2)&1 ; c2: batch ob2

    float xc0 = 0.f, xc1 = 0.f;
    if (!half) {
        const float* g0 = g_xg + (size_t)bb * 256 + p;
        xc0 = g0[0]; xc1 = g0[256];
    }

    for (int t = 0; t < TT; ++t) {
        // prefetch xg for t+1 (hidden under this step)
        float xn0 = 0.f, xn1 = 0.f;
        if (!half && t + 1 < TT) {
            const float* gx = g_xg + ((size_t)(t + 1) * NB + bb) * 256 + p;
            xn0 = gx[0]; xn1 = gx[256];
        }

        // ---- layer 1 ----
        const float* pb = h1s + ((t + 1) & 1) * 144 + half * 36;
        ull aA0 = half ? 0ull : pk(xc0, 0.f);
        ull aA1 = half ? 0ull : pk(xc1, 0.f);
        #pragma unroll
        for (int k = 0; k < 8; k++) {
            ulonglong2 ua = *(const ulonglong2*)(pb + k * 4);
            ulonglong2 ub = *(const ulonglong2*)(pb + 72 + k * 4);
            fma2(aA0, w1p[2*k],   ua.x);
            fma2(aA0, w1p[2*k+1], ua.y);
            fma2(aA1, w1p[2*k],   ub.x);
            fma2(aA1, w1p[2*k+1], ub.y);
        }
        float2 s0 = unpk(aA0), s1 = unpk(aA1);
        float A0 = s0.x + s0.y;  A0 += __shfl_xor_sync(FULL, A0, 1);
        float A1 = s1.x + s1.y;  A1 += __shfl_xor_sync(FULL, A1, 1);
        float act0 = fmaf(ms1, tanhapx(km1 * A0), md1);
        float act1 = fmaf(ms1, tanhapx(km1 * A1), md1);
        float v = (lane & 1) ? act1 : act0;
        float gi = __shfl_sync(FULL, v, sb1 + 0);
        float gf = __shfl_sync(FULL, v, sb1 + 2);
        float gg = __shfl_sync(FULL, v, sb1 + 4);
        float go = __shfl_sync(FULL, v, sb1 + 6);
        float h1v = cell_rest(gi, gf, gg, go, c1);
        if ((lane & 7) == 0) h1s[(t & 1) * 144 + wpos]      = h1v;   // batch0
        if ((lane & 7) == 4) h1s[(t & 1) * 144 + 72 + wpos] = h1v;   // batch1

        __syncthreads();   // single per-step barrier

        // ---- layer 2 (R=2) ----
        const float* ab = (k2 < 2)
            ? (h1s + (t & 1) * 144 + (k2 & 1) * 36)
            : (h2s + ((t + 1) & 1) * 144 + (k2 & 1) * 36);
        ull cA0 = 0ull, cA1 = 0ull, cB0 = 0ull, cB1 = 0ull;
        #pragma unroll
        for (int m = 0; m < 8; m++) {
            ulonglong2 ua = *(const ulonglong2*)(ab + m * 4);
            ulonglong2 ub = *(const ulonglong2*)(ab + 72 + m * 4);
            fma2(cA0, wA[2*m],   ua.x);
            fma2(cA0, wA[2*m+1], ua.y);
            fma2(cA1, wA[2*m],   ub.x);
            fma2(cA1, wA[2*m+1], ub.y);
            fma2(cB0, wB[2*m],   ua.x);
            fma2(cB0, wB[2*m+1], ua.y);
            fma2(cB1, wB[2*m],   ub.x);
            fma2(cB1, wB[2*m+1], ub.y);
        }
        float2 xA0 = unpk(cA0), xA1 = unpk(cA1), xB0 = unpk(cB0), xB1 = unpk(cB1);
        float sA0 = xA0.x + xA0.y, sA1 = xA1.x + xA1.y;
        float sB0 = xB0.x + xB0.y, sB1 = xB1.x + xB1.y;
        // xor(2): sum chunk pairs {k, k^2}
        sA0 += __shfl_xor_sync(FULL, sA0, 2);
        sA1 += __shfl_xor_sync(FULL, sA1, 2);
        sB0 += __shfl_xor_sync(FULL, sB0, 2);
        sB1 += __shfl_xor_sync(FULL, sB1, 2);
        // xor(1): reduce-scatter to owned (row, batch)
        float tb0 = (k2 >= 2) ? sB0 : sA0;     // my row, batch0 partial
        float tb1 = (k2 >= 2) ? sB1 : sA1;     // my row, batch1 partial
        float snd = ob2 ? tb0 : tb1;           // send other batch
        float rcv = __shfl_xor_sync(FULL, snd, 1);
        float Afin = (ob2 ? tb1 : tb0) + rcv + bias2;
        float act2 = fmaf(ms2, tanhapx(km2 * Afin), md2);
        float Gi = __shfl_sync(FULL, act2, sb2 + 0);
        float Gf = __shfl_sync(FULL, act2, sb2 + 2);
        float Gg = __shfl_sync(FULL, act2, sb2 + 4);
        float Go = __shfl_sync(FULL, act2, sb2 + 6);
        float h2v = cell_rest(Gi, Gf, Gg, Go, c2);
        if (j8 == 0) {
            h2s[(t & 1) * 144 + wpos] = h2v;
            g_h2[((size_t)bb * TT + t) * 64 + h] = h2v;
        }
        if (j8 == 1) {
            h2s[(t & 1) * 144 + 72 + wpos] = h2v;
            g_h2[(((size_t)bb + 1) * TT + t) * 64 + h] = h2v;
        }

        xc0 = xn0; xc1 = xn1;
    }
}

// ---------------- Kernel 3: y head ----------------
__global__ void __launch_bounds__(256, 1)
yhead_kernel(const float* __restrict__ Wout, const float* __restrict__ bOut,
             float* __restrict__ out)
{
    __shared__ float w[64];
    __shared__ float bsh;
    if (threadIdx.x < 64) w[threadIdx.x] = Wout[threadIdx.x];
    if (threadIdx.x == 0) bsh = bOut[0];
    __syncthreads();

    int idx = blockIdx.x * 256 + threadIdx.x;     // [b][t]
    const float* hp = g_h2 + (size_t)idx * 64;
    float s = bsh;
    #pragma unroll
    for (int k = 0; k < 16; k++) {
        float4 vv = *(const float4*)(hp + 4 * k);
        s += vv.x * w[4*k] + vv.y * w[4*k+1] + vv.z * w[4*k+2] + vv.w * w[4*k+3];
    }
    out[idx] = fminf(fmaxf(s, 0.f), 1.f);
}

extern "C" void kernel_launch(void* const* d_in, const int* in_sizes, int n_in,
                              void* d_out, int out_size)
{
    (void)in_sizes; (void)n_in; (void)out_size;
    const float* x    = (const float*)d_in[0];
    const float* Wih0 = (const float*)d_in[1];
    const float* Whh0 = (const float*)d_in[2];
    const float* bih0 = (const float*)d_in[3];
    const float* bhh0 = (const float*)d_in[4];
    const float* Wih1 = (const float*)d_in[5];
    const float* Whh1 = (const float*)d_in[6];
    const float* bih1 = (const float*)d_in[7];
    const float* bhh1 = (const float*)d_in[8];
    const float* Wout = (const float*)d_in[9];
    const float* bOut = (const float*)d_in[10];
    float* out = (float*)d_out;

    xg_kernel<<<2048, 256>>>(x, Wih0, bih0, bhh0);
    lstm2_kernel<<<128, 512>>>(Whh0, Wih1, Whh1, bih1, bhh1);
    yhead_kernel<<<2048, 256>>>(Wout, bOut, out);
}